// round 6
// baseline (speedup 1.0000x reference)
#include <cuda_runtime.h>

namespace {

constexpr int NT = 32;   // one warp per block; smem = 11.1KB -> ~20 blocks/SM

struct X {
    float r0, r1, r2, r3, r4, r5, r6, r7, r8;  // 3x3 rotation, row-major
    float tx, ty, tz;                           // translation
};

// Local transform from (unnormalized) quat (w,x,y,z) + position.
// s = 2/|q|^2 — identical to normalize-then-rotmat.
__device__ __forceinline__ X make_local(float4 q, float px, float py, float pz) {
    X o;
    float n = q.x * q.x + q.y * q.y + q.z * q.z + q.w * q.w;
    float s = __fdividef(2.0f, n);
    // q.x=w q.y=x q.z=y q.w=z (reference order)
    float x2 = q.y * s, y2 = q.z * s, z2 = q.w * s;
    float xx = q.y * x2, yy = q.z * y2, zz = q.w * z2;
    float xy = q.y * y2, yz = q.z * z2, xz = q.y * z2;
    float wx = q.x * x2, wy = q.x * y2, wz = q.x * z2;
    o.r0 = 1.0f - (yy + zz); o.r1 = xy - wz;          o.r2 = xz + wy;
    o.r3 = xy + wz;          o.r4 = 1.0f - (xx + zz); o.r5 = yz - wx;
    o.r6 = xz - wy;          o.r7 = yz + wx;          o.r8 = 1.0f - (xx + yy);
    o.tx = px; o.ty = py; o.tz = pz;
    return o;
}

__device__ __forceinline__ X xmul(const X& a, const X& b) {
    X c;
    c.r0 = a.r0 * b.r0 + a.r1 * b.r3 + a.r2 * b.r6;
    c.r1 = a.r0 * b.r1 + a.r1 * b.r4 + a.r2 * b.r7;
    c.r2 = a.r0 * b.r2 + a.r1 * b.r5 + a.r2 * b.r8;
    c.r3 = a.r3 * b.r0 + a.r4 * b.r3 + a.r5 * b.r6;
    c.r4 = a.r3 * b.r1 + a.r4 * b.r4 + a.r5 * b.r7;
    c.r5 = a.r3 * b.r2 + a.r4 * b.r5 + a.r5 * b.r8;
    c.r6 = a.r6 * b.r0 + a.r7 * b.r3 + a.r8 * b.r6;
    c.r7 = a.r6 * b.r1 + a.r7 * b.r4 + a.r8 * b.r7;
    c.r8 = a.r6 * b.r2 + a.r7 * b.r5 + a.r8 * b.r8;
    c.tx = a.r0 * b.tx + a.r1 * b.ty + a.r2 * b.tz + a.tx;
    c.ty = a.r3 * b.tx + a.r4 * b.ty + a.r5 * b.tz + a.ty;
    c.tz = a.r6 * b.tx + a.r7 * b.ty + a.r8 * b.tz + a.tz;
    return c;
}

}  // namespace

__global__ void __launch_bounds__(NT) fk_kernel(
    const float* __restrict__ pos,   // [B,24,3]
    const float* __restrict__ rot,   // [B,24,4]
    float* __restrict__ out,         // [B,24,3]
    int B)
{
    // Per-pass buffers (pass = 12-joint half of the tree).
    // A: scalar rows, stride 33 ≡ 1 (mod 32) -> per-thread column access conflict-free.
    // Q4: float4-native; compute reads LDS.128 (lanes consecutive 16B, conflict-free).
    __shared__ float  A[36][NT + 1];
    __shared__ float4 Q4[12][NT + 1];

    const int tid = threadIdx.x;
    const int blockBase = blockIdx.x * NT;
    const int nb = min(NT, B - blockBase);
    const int nfp = nb * 9;    // pos float4s per pass
    const int nfq = nb * 12;   // quat float4s per pass

    const float4* gp4 = (const float4*)(pos + (size_t)blockBase * 72);
    const float4* gq4 = (const float4*)(rot + (size_t)blockBase * 96);
    float4* go4 = (float4*)(out + (size_t)blockBase * 72);

    auto stage = [&](int pass) {
#pragma unroll
        for (int i = 0; i < 9; ++i) {            // positions half
            int f = i * NT + tid;
            if (f < nfp) {
                int b = f / 9, k = f - b * 9;
                float4 v = __ldg(&gp4[b * 18 + pass * 9 + k]);
                A[4 * k + 0][b] = v.x;
                A[4 * k + 1][b] = v.y;
                A[4 * k + 2][b] = v.z;
                A[4 * k + 3][b] = v.w;
            }
        }
#pragma unroll
        for (int i = 0; i < 12; ++i) {           // quats half (leaf quats skipped)
            int f = i * NT + tid;
            if (f < nfq) {
                int b = f / 12, jj = f - b * 12;
                // leaves: pass0 joints 10,11 (jj 10,11); pass1 joints 15,22,23 (jj 3,10,11)
                bool need = (pass == 0) ? (jj < 10) : (jj != 3 && jj < 10);
                if (need) Q4[jj][b] = __ldg(&gq4[b * 24 + pass * 12 + jj]);
            }
        }
    };
    auto flush = [&](int pass) {
#pragma unroll
        for (int i = 0; i < 9; ++i) {
            int f = i * NT + tid;
            if (f < nfp) {
                int b = f / 9, k = f - b * 9;
                float4 v;
                v.x = A[4 * k + 0][b];
                v.y = A[4 * k + 1][b];
                v.z = A[4 * k + 2][b];
                v.w = A[4 * k + 3][b];
                go4[b * 18 + pass * 9 + k] = v;
            }
        }
    };

    // jj = joint index within the pass's 12-joint window.
    auto local = [&](int jj) -> X {
        float4 q = Q4[jj][tid];   // single LDS.128
        return make_local(q, A[3 * jj + 0][tid], A[3 * jj + 1][tid],
                          A[3 * jj + 2][tid]);
    };
    auto putx = [&](int jj, const X& g) {   // output aliases consumed pos rows
        A[3 * jj + 0][tid] = g.tx;
        A[3 * jj + 1][tid] = g.ty;
        A[3 * jj + 2][tid] = g.tz;
    };
    auto putleaf = [&](int jj, const X& a) {  // leaf: translation only, no quat
        float px = A[3 * jj + 0][tid], py = A[3 * jj + 1][tid],
              pz = A[3 * jj + 2][tid];
        A[3 * jj + 0][tid] = a.r0 * px + a.r1 * py + a.r2 * pz + a.tx;
        A[3 * jj + 1][tid] = a.r3 * px + a.r4 * py + a.r5 * pz + a.ty;
        A[3 * jj + 2][tid] = a.r6 * px + a.r7 * py + a.r8 * pz + a.tz;
    };

    X g9;  // persists across passes in registers

    // ================= Pass 1: joints 0..11 =================
    stage(0);
    __syncthreads();   // nw=1: ~3 cyc
    if (tid < nb) {
        X g0 = local(0);
        putx(0, g0);
        {
            X a = xmul(g0, local(1)); putx(1, a);
            a = xmul(a, local(4));    putx(4, a);
            a = xmul(a, local(7));    putx(7, a);
            putleaf(10, a);
        }
        {
            X a = xmul(g0, local(2)); putx(2, a);
            a = xmul(a, local(5));    putx(5, a);
            a = xmul(a, local(8));    putx(8, a);
            putleaf(11, a);
        }
        {
            X a = xmul(g0, local(3)); putx(3, a);
            a = xmul(a, local(6));    putx(6, a);
            g9 = xmul(a, local(9));   putx(9, g9);
        }
    }
    __syncthreads();
    flush(0);
    __syncthreads();

    // ================= Pass 2: joints 12..23 (jj = j-12) =================
    stage(1);
    __syncthreads();
    if (tid < nb) {
        {
            X a = xmul(g9, local(0));  putx(0, a);   // 12
            putleaf(3, a);                            // 15
        }
        {
            X a = xmul(g9, local(1));  putx(1, a);   // 13
            a = xmul(a, local(4));     putx(4, a);   // 16
            a = xmul(a, local(6));     putx(6, a);   // 18
            a = xmul(a, local(8));     putx(8, a);   // 20
            putleaf(10, a);                           // 22
        }
        {
            X a = xmul(g9, local(2));  putx(2, a);   // 14
            a = xmul(a, local(5));     putx(5, a);   // 17
            a = xmul(a, local(7));     putx(7, a);   // 19
            a = xmul(a, local(9));     putx(9, a);   // 21
            putleaf(11, a);                           // 23
        }
    }
    __syncthreads();
    flush(1);
}

extern "C" void kernel_launch(void* const* d_in, const int* in_sizes, int n_in,
                              void* d_out, int out_size) {
    // metadata order: parents (int64, unused — tree is compile-time),
    //                 positions (B*24*3 f32), rotations (B*24*4 f32)
    const float* pos = (const float*)d_in[1];
    const float* rot = (const float*)d_in[2];
    float* out = (float*)d_out;

    int B = in_sizes[1] / 72;
    int grid = (B + NT - 1) / NT;
    fk_kernel<<<grid, NT>>>(pos, rot, out, B);
}